// round 9
// baseline (speedup 1.0000x reference)
#include <cuda_runtime.h>
#include <math.h>

#define BS_    64
#define KK_    4
#define PTS_   5
#define RES_   28
#define STEPS_ 500
#define NT_    512
#define NW_    16           // warps per CTA
#define NB_    8            // partial buffers after staged merge
#define KSTEPS_ 63          // ceil(504/8)
#define KPAD_  504
#define PIX_ (RES_*RES_)    // 784
#define PSTR_ 34            // padded row stride of C partial
#define PWARP_ (32*PSTR_)   // 1088 floats per buffer

// staging: tanh-normed strokes per (b,k)
__device__ float g_stage[BS_ * KK_ * PIX_];
// per-batch arrival counters for fused compose (zero-init; reset each run)
__device__ unsigned int g_cnt[BS_];

__device__ __forceinline__ void mma_tf32(float* d,
                                         unsigned a0, unsigned a1, unsigned a2, unsigned a3,
                                         unsigned b0, unsigned b1) {
    asm volatile(
        "mma.sync.aligned.m16n8k8.row.col.f32.tf32.tf32.f32 "
        "{%0,%1,%2,%3}, {%4,%5,%6,%7}, {%8,%9}, {%0,%1,%2,%3};"
        : "+f"(d[0]), "+f"(d[1]), "+f"(d[2]), "+f"(d[3])
        : "r"(a0), "r"(a1), "r"(a2), "r"(a3), "r"(b0), "r"(b1));
}
__device__ __forceinline__ float ex2f(float x) {
    float r; asm("ex2.approx.ftz.f32 %0, %1;" : "=f"(r) : "f"(x)); return r;
}
__device__ __forceinline__ float rcpf(float x) {
    float r; asm("rcp.approx.ftz.f32 %0, %1;" : "=f"(r) : "f"(x)); return r;
}
// tanh(x) = 1 - 2/(exp(2x)+1), x >= 0 here (inputs are >= 0 scaled values)
__device__ __forceinline__ float fast_tanh(float x) {
    const float e = ex2f(x * 2.88539008177793f);   // exp(2x)
    return 1.0f - 2.0f * rcpf(e + 1.0f);
}

__global__ __launch_bounds__(NT_, 2)
void guide_mma_kernel(const float* __restrict__ z_pres,
                      const float* __restrict__ z_what,
                      const float* __restrict__ z_where,
                      const float* __restrict__ sigma_p,
                      const float* __restrict__ slope_strk_p,
                      const float* __restrict__ slope_p,
                      float* __restrict__ out)
{
    __shared__ float2 curve[KPAD_];          // (cx, cy) per t
    __shared__ float  part[NB_ * PWARP_];    // per-buffer C partials (32x34)
    __shared__ float  red[16];
    __shared__ unsigned int slast;

    const int bk   = blockIdx.x;             // 0..255 = b*4 + k
    const int tid  = threadIdx.x;
    const int wid  = tid >> 5;
    const int lane = tid & 31;
    const int gr   = lane >> 2;              // groupID 0..7
    const int tc   = lane & 3;               // thread-in-group 0..3

    // ---- transform params (uniform) ----
    const float s   = z_where[bk * 3 + 0];
    const float sh0 = z_where[bk * 3 + 1];
    const float sh1 = z_where[bk * 3 + 2];

    float px0, px1, px2, px3, px4, py0, py1, py2, py3, py4;
    {
        const float* w = z_what + bk * PTS_ * 2;
        px0 = w[0] * s + sh0;  py0 = w[1] * s + sh1;
        px1 = w[2] * s + sh0;  py1 = w[3] * s + sh1;
        px2 = w[4] * s + sh0;  py2 = w[5] * s + sh1;
        px3 = w[6] * s + sh0;  py3 = w[7] * s + sh1;
        px4 = w[8] * s + sh0;  py4 = w[9] * s + sh1;
    }
    const float sigma = *sigma_p;
    // fold log2(e) so exp(-d^2*inv) == ex2(d^2 * ninv2)
    const float ninv2 = (-1.0f / (2.0f * sigma * sigma)) * 1.44269504088896f;

    // ---- precompute curve (cx,cy) for all padded t ----
    if (tid < KPAD_) {
        const int k = tid;
        float cx = 1e9f, cy = 1e9f;
        if (k < STEPS_) {
            const float u  = (float)k * (1.0f / (float)(STEPS_ - 1));
            const float v  = 1.0f - u;
            const float u2 = u * u, v2 = v * v;
            const float b0 = v2 * v2;
            const float b1 = 4.0f * u * (v * v2);
            const float b2 = 6.0f * u2 * v2;
            const float b3 = 4.0f * (u2 * u) * v;
            const float b4 = u2 * u2;
            cx = b0*px0 + b1*px1 + b2*px2 + b3*px3 + b4*px4;
            cy = b0*py0 + b1*py1 + b2*py2 + b3*py3 + b4*py4;
        }
        curve[k] = make_float2(cx, cy);
    }
    __syncthreads();

    // per-lane grid values for rows/cols {gr, gr+8, gr+16, gr+24}
    float gv[4];
    gv[0] = (float)gr        * (1.0f / 27.0f);
    gv[1] = (float)(gr + 8)  * (1.0f / 27.0f);
    gv[2] = (float)(gr + 16) * (1.0f / 27.0f);
    gv[3] = (gr < 4) ? (float)(gr + 24) * (1.0f / 27.0f) : 1e6f;

    // accumulators: D[mt][nt][4]
    float D[2][4][4];
#pragma unroll
    for (int mt = 0; mt < 2; mt++)
#pragma unroll
        for (int nt = 0; nt < 4; nt++)
#pragma unroll
            for (int r = 0; r < 4; r++) D[mt][nt][r] = 0.0f;

    // ---- main k-split MMA loop: warp wid owns ksteps [wid*4, min(+4,63)) ----
    const int ks0 = wid * 4;
    const int ks1 = (ks0 + 4 < KSTEPS_) ? ks0 + 4 : KSTEPS_;
    const float2* cp = curve + ks0 * 8 + tc;
#pragma unroll 1
    for (int ks = ks0; ks < ks1; ks++) {
        const float2 cA = cp[0];
        const float2 cB = cp[4];
        cp += 8;

        // 16 exps: ey[r][kk] (A operands), ex[r][kk] (B operands)
        unsigned ey[4][2], ex[4][2];
#pragma unroll
        for (int r = 0; r < 4; r++) {
            float d0 = gv[r] - cA.y;  ey[r][0] = __float_as_uint(ex2f(d0 * d0 * ninv2));
            float d1 = gv[r] - cB.y;  ey[r][1] = __float_as_uint(ex2f(d1 * d1 * ninv2));
            float d2 = gv[r] - cA.x;  ex[r][0] = __float_as_uint(ex2f(d2 * d2 * ninv2));
            float d3 = gv[r] - cB.x;  ex[r][1] = __float_as_uint(ex2f(d3 * d3 * ninv2));
        }

        // 8 tiles x 1 MMA (raw fp32 bits as tf32; truncation bias cancels in maxnorm)
#pragma unroll
        for (int mt = 0; mt < 2; mt++) {
            const unsigned a0 = ey[2*mt][0], a1 = ey[2*mt+1][0];
            const unsigned a2 = ey[2*mt][1], a3 = ey[2*mt+1][1];
#pragma unroll
            for (int nt = 0; nt < 4; nt++)
                mma_tf32(D[mt][nt], a0, a1, a2, a3, ex[nt][0], ex[nt][1]);
        }
    }

    // ---- staged merge: warps 8-15 store, then warps 0-7 add ----
    {
        float* wp = part + (wid & 7) * PWARP_;
        if (wid >= NB_) {
#pragma unroll
            for (int mt = 0; mt < 2; mt++)
#pragma unroll
                for (int nt = 0; nt < 4; nt++) {
                    const int row = mt * 16 + gr;
                    const int col = nt * 8 + 2 * tc;
                    float* b0 = wp + row * PSTR_ + col;
                    b0[0] = D[mt][nt][0];
                    b0[1] = D[mt][nt][1];
                    b0[8 * PSTR_]     = D[mt][nt][2];
                    b0[8 * PSTR_ + 1] = D[mt][nt][3];
                }
        }
        __syncthreads();
        if (wid < NB_) {
#pragma unroll
            for (int mt = 0; mt < 2; mt++)
#pragma unroll
                for (int nt = 0; nt < 4; nt++) {
                    const int row = mt * 16 + gr;
                    const int col = nt * 8 + 2 * tc;
                    float* b0 = wp + row * PSTR_ + col;
                    b0[0] += D[mt][nt][0];
                    b0[1] += D[mt][nt][1];
                    b0[8 * PSTR_]     += D[mt][nt][2];
                    b0[8 * PSTR_ + 1] += D[mt][nt][3];
                }
        }
    }
    __syncthreads();

    // ---- epilogue: sum buffers, z_pres scale, maxnorm, tanh-norm, stage ----
    const float zp = z_pres[bk];
    float myv[2];
    float lmax = 0.0f;
#pragma unroll
    for (int r = 0; r < 2; r++) {
        const int p = r * NT_ + tid;
        float v = 0.0f;
        if (p < PIX_) {
            const int y = p / RES_;
            const int x = p - y * RES_;
            const int o = y * PSTR_ + x;
            v = part[o];
#pragma unroll
            for (int w = 1; w < NB_; w++) v += part[w * PWARP_ + o];
            v *= zp;
        }
        myv[r] = v;
        lmax = fmaxf(lmax, v);
    }
#pragma unroll
    for (int o = 16; o > 0; o >>= 1)
        lmax = fmaxf(lmax, __shfl_xor_sync(0xffffffffu, lmax, o));
    if ((tid & 31) == 0) red[tid >> 5] = lmax;
    __syncthreads();
    float bmax = red[0];
#pragma unroll
    for (int w = 1; w < 16; w++) bmax = fmaxf(bmax, red[w]);

    const float scale = 1.0f / (bmax + 1e-6f);
    const float sl    = *slope_strk_p;
    const float itsl  = rcpf(fast_tanh(sl));
    float* stage = g_stage + bk * PIX_;
#pragma unroll
    for (int r = 0; r < 2; r++) {
        const int p = r * NT_ + tid;
        if (p < PIX_)
            stage[p] = fast_tanh(myv[r] * scale * sl) * itsl;
    }

    // ---- fused compose: last CTA of each batch composes the image ----
    if (tid == 0) {
        __threadfence();   // publish stage writes before arrival
        unsigned int old = atomicAdd(&g_cnt[bk >> 2], 1u);
        slast = (old == 3u) ? 1u : 0u;
    }
    __syncthreads();
    if (slast) {
        __threadfence();   // acquire: see peer CTAs' stage writes
        const int b = bk >> 2;
        const float* st = g_stage + b * KK_ * PIX_;
        const float sl2 = *slope_p;
        const float it2 = rcpf(fast_tanh(sl2));
        for (int p = tid; p < PIX_; p += NT_) {
            const float ssum = st[p] + st[PIX_ + p] + st[2*PIX_ + p] + st[3*PIX_ + p];
            out[b * PIX_ + p] = fast_tanh(ssum * sl2) * it2;
        }
        if (tid == 0) g_cnt[b] = 0u;   // reset for next (graph-replayed) call
    }
}

extern "C" void kernel_launch(void* const* d_in, const int* in_sizes, int n_in,
                              void* d_out, int out_size)
{
    const float* z_pres     = (const float*)d_in[0];
    const float* z_what     = (const float*)d_in[1];
    const float* z_where    = (const float*)d_in[2];
    const float* sigma      = (const float*)d_in[3];
    const float* slope_strk = (const float*)d_in[4];
    const float* slope      = (const float*)d_in[5];
    float* out = (float*)d_out;

    guide_mma_kernel<<<BS_ * KK_, NT_>>>(z_pres, z_what, z_where,
                                         sigma, slope_strk, slope, out);
}

// round 10
// speedup vs baseline: 1.0025x; 1.0025x over previous
#include <cuda_runtime.h>
#include <math.h>

#define BS_    64
#define KK_    4
#define PTS_   5
#define RES_   28
#define STEPS_ 500
#define NT_    512
#define KSTEPS_ 63          // ceil(504/8)
#define KPAD_  504
#define PIX_ (RES_*RES_)    // 784
#define PSTR_ 34            // padded row stride of C partial
#define PWARP_ (32*PSTR_)   // 1088 floats per buffer

// staging: tanh-normed strokes per (b,k)
__device__ float g_stage[BS_ * KK_ * PIX_];
// per-batch pair counters for fused compose (zero-init; reset each run)
__device__ unsigned int g_cnt[BS_];

__device__ __forceinline__ void mma_tf32(float* d,
                                         unsigned a0, unsigned a1, unsigned a2, unsigned a3,
                                         unsigned b0, unsigned b1) {
    asm volatile(
        "mma.sync.aligned.m16n8k8.row.col.f32.tf32.tf32.f32 "
        "{%0,%1,%2,%3}, {%4,%5,%6,%7}, {%8,%9}, {%0,%1,%2,%3};"
        : "+f"(d[0]), "+f"(d[1]), "+f"(d[2]), "+f"(d[3])
        : "r"(a0), "r"(a1), "r"(a2), "r"(a3), "r"(b0), "r"(b1));
}
__device__ __forceinline__ float ex2f(float x) {
    float r; asm("ex2.approx.ftz.f32 %0, %1;" : "=f"(r) : "f"(x)); return r;
}
__device__ __forceinline__ float rcpf(float x) {
    float r; asm("rcp.approx.ftz.f32 %0, %1;" : "=f"(r) : "f"(x)); return r;
}
// tanh(x) for x >= 0: 1 - 2/(exp(2x)+1)
__device__ __forceinline__ float fast_tanh(float x) {
    const float e = ex2f(x * 2.88539008177793f);
    return 1.0f - 2.0f * rcpf(e + 1.0f);
}

__global__ __launch_bounds__(NT_, 1)
void guide_mma_kernel(const float* __restrict__ z_pres,
                      const float* __restrict__ z_what,
                      const float* __restrict__ z_where,
                      const float* __restrict__ sigma_p,
                      const float* __restrict__ slope_strk_p,
                      const float* __restrict__ slope_p,
                      float* __restrict__ out)
{
    __shared__ float2 curve[2 * KPAD_];      // (cx,cy) per t, per local stroke
    __shared__ float  part[8 * PWARP_];      // 4 buffers x 2 strokes (32x34 each)
    __shared__ float  red[32];               // per-warp {max0, max1}
    __shared__ unsigned int slast;

    const int bid    = blockIdx.x;           // 0..127
    const int b      = bid >> 1;
    const int pr     = bid & 1;              // k-pair: strokes {2pr, 2pr+1}
    const int bkbase = b * KK_ + pr * 2;
    const int tid  = threadIdx.x;
    const int wid  = tid >> 5;
    const int lane = tid & 31;
    const int gr   = lane >> 2;              // groupID 0..7
    const int tc   = lane & 3;               // thread-in-group 0..3

    const float sigma = *sigma_p;
    const float ninv2 = (-1.0f / (2.0f * sigma * sigma)) * 1.44269504088896f;

    // ---- load transform params for both local strokes ----
    float px[2][5], py[2][5];
#pragma unroll
    for (int sk = 0; sk < 2; sk++) {
        const int bk = bkbase + sk;
        const float s   = z_where[bk * 3 + 0];
        const float s0  = z_where[bk * 3 + 1];
        const float s1  = z_where[bk * 3 + 2];
        const float* w = z_what + bk * PTS_ * 2;
#pragma unroll
        for (int i = 0; i < 5; i++) {
            px[sk][i] = w[2*i]   * s + s0;
            py[sk][i] = w[2*i+1] * s + s1;
        }
    }

    // ---- precompute curves for both strokes (1008 entries / 512 threads) ----
#pragma unroll
    for (int c = 0; c < 2; c++) {
        const int e = tid + c * NT_;
        if (e < 2 * KPAD_) {
            const int sk = (e >= KPAD_) ? 1 : 0;
            const int k  = e - sk * KPAD_;
            float cx = 1e9f, cy = 1e9f;
            if (k < STEPS_) {
                const float u  = (float)k * (1.0f / (float)(STEPS_ - 1));
                const float v  = 1.0f - u;
                const float u2 = u * u, v2 = v * v;
                const float b0 = v2 * v2;
                const float b1 = 4.0f * u * (v * v2);
                const float b2 = 6.0f * u2 * v2;
                const float b3 = 4.0f * (u2 * u) * v;
                const float b4 = u2 * u2;
                cx = b0*px[sk][0] + b1*px[sk][1] + b2*px[sk][2] + b3*px[sk][3] + b4*px[sk][4];
                cy = b0*py[sk][0] + b1*py[sk][1] + b2*py[sk][2] + b3*py[sk][3] + b4*py[sk][4];
            }
            curve[e] = make_float2(cx, cy);
        }
    }
    __syncthreads();

    // per-lane grid values for rows/cols {gr, gr+8, gr+16, gr+24}
    float gv[4];
    gv[0] = (float)gr        * (1.0f / 27.0f);
    gv[1] = (float)(gr + 8)  * (1.0f / 27.0f);
    gv[2] = (float)(gr + 16) * (1.0f / 27.0f);
    gv[3] = (gr < 4) ? (float)(gr + 24) * (1.0f / 27.0f) : 1e6f;

    float D[2][4][4];
#pragma unroll
    for (int mt = 0; mt < 2; mt++)
#pragma unroll
        for (int nt = 0; nt < 4; nt++)
#pragma unroll
            for (int r = 0; r < 4; r++) D[mt][nt][r] = 0.0f;

    // ---- mainloop: warp wid -> stroke (wid&1), ksteps [(wid>>1)*8, +8) ----
    const int sk  = wid & 1;
    const int grp = wid >> 1;                // 0..7
    const int ks0 = grp * 8;
    const int ks1 = (ks0 + 8 < KSTEPS_) ? ks0 + 8 : KSTEPS_;
    const float2* cp = curve + sk * KPAD_ + ks0 * 8 + tc;
#pragma unroll 1
    for (int ks = ks0; ks < ks1; ks++) {
        const float2 cA = cp[0];
        const float2 cB = cp[4];
        cp += 8;

        unsigned ey[4][2], ex[4][2];
#pragma unroll
        for (int r = 0; r < 4; r++) {
            float d0 = gv[r] - cA.y;  ey[r][0] = __float_as_uint(ex2f(d0 * d0 * ninv2));
            float d1 = gv[r] - cB.y;  ey[r][1] = __float_as_uint(ex2f(d1 * d1 * ninv2));
            float d2 = gv[r] - cA.x;  ex[r][0] = __float_as_uint(ex2f(d2 * d2 * ninv2));
            float d3 = gv[r] - cB.x;  ex[r][1] = __float_as_uint(ex2f(d3 * d3 * ninv2));
        }

#pragma unroll
        for (int mt = 0; mt < 2; mt++) {
            const unsigned a0 = ey[2*mt][0], a1 = ey[2*mt+1][0];
            const unsigned a2 = ey[2*mt][1], a3 = ey[2*mt+1][1];
#pragma unroll
            for (int nt = 0; nt < 4; nt++)
                mma_tf32(D[mt][nt], a0, a1, a2, a3, ex[nt][0], ex[nt][1]);
        }
    }

    // ---- staged merge: grp 4-7 store, grp 0-3 add (per stroke, 4 buffers) ----
    {
        float* wp = part + (sk * 4 + (grp & 3)) * PWARP_;
        if (grp >= 4) {
#pragma unroll
            for (int mt = 0; mt < 2; mt++)
#pragma unroll
                for (int nt = 0; nt < 4; nt++) {
                    const int row = mt * 16 + gr;
                    const int col = nt * 8 + 2 * tc;
                    float* b0 = wp + row * PSTR_ + col;
                    b0[0] = D[mt][nt][0];
                    b0[1] = D[mt][nt][1];
                    b0[8 * PSTR_]     = D[mt][nt][2];
                    b0[8 * PSTR_ + 1] = D[mt][nt][3];
                }
        }
        __syncthreads();
        if (grp < 4) {
#pragma unroll
            for (int mt = 0; mt < 2; mt++)
#pragma unroll
                for (int nt = 0; nt < 4; nt++) {
                    const int row = mt * 16 + gr;
                    const int col = nt * 8 + 2 * tc;
                    float* b0 = wp + row * PSTR_ + col;
                    b0[0] += D[mt][nt][0];
                    b0[1] += D[mt][nt][1];
                    b0[8 * PSTR_]     += D[mt][nt][2];
                    b0[8 * PSTR_ + 1] += D[mt][nt][3];
                }
        }
    }
    __syncthreads();

    // ---- epilogue: both strokes — sum buffers, zp scale, block max ----
    const float zp0 = z_pres[bkbase];
    const float zp1 = z_pres[bkbase + 1];
    float myv[2][2];
    float lmax0 = 0.0f, lmax1 = 0.0f;
#pragma unroll
    for (int r = 0; r < 2; r++) {
        const int p = r * NT_ + tid;
        float v0 = 0.0f, v1 = 0.0f;
        if (p < PIX_) {
            const int y = p / RES_;
            const int x = p - y * RES_;
            const int o = y * PSTR_ + x;
            v0 = (part[o] + part[PWARP_ + o] + part[2*PWARP_ + o] + part[3*PWARP_ + o]) * zp0;
            v1 = (part[4*PWARP_ + o] + part[5*PWARP_ + o] + part[6*PWARP_ + o] + part[7*PWARP_ + o]) * zp1;
        }
        myv[0][r] = v0;  myv[1][r] = v1;
        lmax0 = fmaxf(lmax0, v0);
        lmax1 = fmaxf(lmax1, v1);
    }
#pragma unroll
    for (int o = 16; o > 0; o >>= 1) {
        lmax0 = fmaxf(lmax0, __shfl_xor_sync(0xffffffffu, lmax0, o));
        lmax1 = fmaxf(lmax1, __shfl_xor_sync(0xffffffffu, lmax1, o));
    }
    if (lane == 0) { red[wid] = lmax0; red[16 + wid] = lmax1; }
    __syncthreads();
    float bmax0 = red[0], bmax1 = red[16];
#pragma unroll
    for (int w = 1; w < 16; w++) {
        bmax0 = fmaxf(bmax0, red[w]);
        bmax1 = fmaxf(bmax1, red[16 + w]);
    }

    const float sl   = *slope_strk_p;
    const float itsl = rcpf(fast_tanh(sl));
    const float sc0  = rcpf(bmax0 + 1e-6f) * sl;   // (1/(m+eps))*sl
    const float sc1  = rcpf(bmax1 + 1e-6f) * sl;
    // NB: rcp.approx on (m+eps) — error ~1e-7 relative, absorbed by tolerance
    float* st0 = g_stage + (bkbase)     * PIX_;
    float* st1 = g_stage + (bkbase + 1) * PIX_;
#pragma unroll
    for (int r = 0; r < 2; r++) {
        const int p = r * NT_ + tid;
        if (p < PIX_) {
            st0[p] = fast_tanh(myv[0][r] * sc0) * itsl;
            st1[p] = fast_tanh(myv[1][r] * sc1) * itsl;
        }
    }

    // ---- pair sync: last of the 2 CTAs of batch b composes the image ----
    if (tid == 0) {
        __threadfence();   // publish stage writes before arrival
        unsigned int old = atomicAdd(&g_cnt[b], 1u);
        slast = (old == 1u) ? 1u : 0u;
    }
    __syncthreads();
    if (slast) {
        __threadfence();   // acquire: see partner CTA's stage writes
        const float* st = g_stage + b * KK_ * PIX_;
        const float sl2 = *slope_p;
        const float it2 = rcpf(fast_tanh(sl2));
#pragma unroll
        for (int r = 0; r < 2; r++) {
            const int p = r * NT_ + tid;
            if (p < PIX_) {
                const float ssum = st[p] + st[PIX_ + p] + st[2*PIX_ + p] + st[3*PIX_ + p];
                out[b * PIX_ + p] = fast_tanh(ssum * sl2) * it2;
            }
        }
        if (tid == 0) g_cnt[b] = 0u;   // reset for next (graph-replayed) call
    }
}

extern "C" void kernel_launch(void* const* d_in, const int* in_sizes, int n_in,
                              void* d_out, int out_size)
{
    const float* z_pres     = (const float*)d_in[0];
    const float* z_what     = (const float*)d_in[1];
    const float* z_where    = (const float*)d_in[2];
    const float* sigma      = (const float*)d_in[3];
    const float* slope_strk = (const float*)d_in[4];
    const float* slope      = (const float*)d_in[5];
    float* out = (float*)d_out;

    guide_mma_kernel<<<2 * BS_, NT_>>>(z_pres, z_what, z_where,
                                       sigma, slope_strk, slope, out);
}